// round 1
// baseline (speedup 1.0000x reference)
#include <cuda_runtime.h>
#include <math.h>

#define NN 50000
#define EE 800000
#define ET (EE + NN)   // edges + self loops
#define DIM 64
#define GG 256
#define CC 10
#define NEG_SLOPE 0.2f

// ---------------- device scratch (static, no allocation) ----------------
__device__ float g_h[NN * DIM];      // h = x @ W  (current layer)
__device__ float g_out[NN * DIM];    // aggregated output / next-layer input
__device__ float g_as[NN];
__device__ float g_ad[NN];
__device__ unsigned int g_emax[NN];  // ordered-uint encoded float max
__device__ float g_denom[NN];
__device__ float g_pool[GG * DIM];
__device__ int g_is64;

// ordered-uint encoding for atomic float max
__device__ __forceinline__ unsigned int fenc(float f) {
    unsigned int u = __float_as_uint(f);
    return (u & 0x80000000u) ? ~u : (u | 0x80000000u);
}
__device__ __forceinline__ float fdec(unsigned int u) {
    return (u & 0x80000000u) ? __uint_as_float(u ^ 0x80000000u)
                             : __uint_as_float(~u);
}

__device__ __forceinline__ void load_edge(const void* ei, int e, int& s, int& d) {
    if (e >= EE) { s = d = e - EE; return; }  // self loop
    if (g_is64) {
        const long long* p = (const long long*)ei;
        s = (int)p[e];
        d = (int)p[EE + e];
    } else {
        const int* p = (const int*)ei;
        s = p[e];
        d = p[EE + e];
    }
}

// ---------------- K0: detect int64 vs int32 indices ----------------
__global__ void k_detect(const void* ei) {
    const int* p = (const int*)ei;
    bool is64 = true;
    for (int k = 0; k < 64; k++) {
        if (p[2 * k + 1] != 0) { is64 = false; break; }
    }
    g_is64 = is64 ? 1 : 0;
}

// ---------------- K1: h = xin @ W, alpha scalars, per-node init ----------------
// grid: NN blocks, 64 threads. xin may alias g_out (layers 2,3): row is read
// into smem BEFORE the g_out row is zeroed.
__global__ void k_gemm_attn(const float* __restrict__ xin,
                            const float* __restrict__ w,
                            const float* __restrict__ a_src,
                            const float* __restrict__ a_dst) {
    __shared__ float xr[DIM];
    __shared__ float r1[DIM];
    __shared__ float r2[DIM];
    int i = blockIdx.x;
    int t = threadIdx.x;
    xr[t] = xin[i * DIM + t];
    __syncthreads();
    // safe to clear aggregation buffer now
    g_out[i * DIM + t] = 0.0f;

    float h = 0.0f;
#pragma unroll
    for (int k = 0; k < DIM; k++) h = fmaf(xr[k], w[k * DIM + t], h);
    g_h[i * DIM + t] = h;

    r1[t] = h * a_src[t];
    r2[t] = h * a_dst[t];
    __syncthreads();
#pragma unroll
    for (int off = 32; off > 0; off >>= 1) {
        if (t < off) { r1[t] += r1[t + off]; r2[t] += r2[t + off]; }
        __syncthreads();
    }
    if (t == 0) {
        g_as[i] = r1[0];
        g_ad[i] = r2[0];
        g_emax[i] = 0u;        // below encode() of any finite float
        g_denom[i] = 0.0f;
    }
}

// ---------------- K2: segment max of leaky_relu(as[src]+ad[dst]) ----------------
__global__ void k_edge_max(const void* __restrict__ ei) {
    int e = blockIdx.x * blockDim.x + threadIdx.x;
    if (e >= ET) return;
    int s, d;
    load_edge(ei, e, s, d);
    float v = g_as[s] + g_ad[d];
    v = (v > 0.0f) ? v : NEG_SLOPE * v;
    atomicMax(&g_emax[d], fenc(v));
}

// ---------------- K3: denom = segment sum of exp(e - emax[dst]) ----------------
__global__ void k_edge_denom(const void* __restrict__ ei) {
    int e = blockIdx.x * blockDim.x + threadIdx.x;
    if (e >= ET) return;
    int s, d;
    load_edge(ei, e, s, d);
    float v = g_as[s] + g_ad[d];
    v = (v > 0.0f) ? v : NEG_SLOPE * v;
    float ex = expf(v - fdec(g_emax[d]));
    atomicAdd(&g_denom[d], ex);
}

// ---------------- K4: out[dst] += alpha * h[src] ----------------
// 256 threads/block = 4 edge-groups of 64 threads
__global__ void k_edge_aggregate(const void* __restrict__ ei) {
    int eg = blockIdx.x * 4 + (threadIdx.x >> 6);
    int t = threadIdx.x & 63;
    if (eg >= ET) return;
    int s, d;
    load_edge(ei, eg, s, d);
    float v = g_as[s] + g_ad[d];
    v = (v > 0.0f) ? v : NEG_SLOPE * v;
    float ex = expf(v - fdec(g_emax[d]));
    float alpha = ex / (g_denom[d] + 1e-16f);
    atomicAdd(&g_out[d * DIM + t], alpha * g_h[s * DIM + t]);
}

// ---------------- K5: out = relu(l2_normalize(out + b)) in place ----------------
__global__ void k_norm_relu(const float* __restrict__ bias) {
    __shared__ float red[DIM];
    int i = blockIdx.x;
    int t = threadIdx.x;
    float v = g_out[i * DIM + t] + bias[t];
    red[t] = v * v;
    __syncthreads();
#pragma unroll
    for (int off = 32; off > 0; off >>= 1) {
        if (t < off) red[t] += red[t + off];
        __syncthreads();
    }
    float nrm = sqrtf(red[0]);
    float o = v / fmaxf(nrm, 1e-12f);
    g_out[i * DIM + t] = fmaxf(o, 0.0f);
}

// ---------------- K6: zero pooled buffer ----------------
__global__ void k_zero_pool() {
    int idx = blockIdx.x * blockDim.x + threadIdx.x;
    if (idx < GG * DIM) g_pool[idx] = 0.0f;
}

// ---------------- K7: global add pool ----------------
__global__ void k_pool(const void* __restrict__ batch) {
    int idx = blockIdx.x * blockDim.x + threadIdx.x;
    if (idx >= NN * DIM) return;
    int i = idx >> 6;
    int t = idx & 63;
    int b;
    if (g_is64) b = (int)((const long long*)batch)[i];
    else        b = ((const int*)batch)[i];
    atomicAdd(&g_pool[b * DIM + t], g_out[idx]);
}

// ---------------- K8: MLP head + log_softmax ----------------
__global__ void k_head(const float* __restrict__ fc1_w, const float* __restrict__ fc1_b,
                       const float* __restrict__ fc2_w, const float* __restrict__ fc2_b,
                       float* __restrict__ out) {
    __shared__ float gv[DIM];
    __shared__ float a1[DIM];
    __shared__ float lg[CC];
    __shared__ float m_s, lse_s;
    int b = blockIdx.x;
    int t = threadIdx.x;
    gv[t] = g_pool[b * DIM + t];
    __syncthreads();

    float a = fc1_b[t];
#pragma unroll
    for (int k = 0; k < DIM; k++) a = fmaf(gv[k], fc1_w[k * DIM + t], a);
    a1[t] = fmaxf(a, 0.0f);
    __syncthreads();

    if (t < CC) {
        float l = fc2_b[t];
#pragma unroll
        for (int k = 0; k < DIM; k++) l = fmaf(a1[k], fc2_w[k * CC + t], l);
        lg[t] = l;
    }
    __syncthreads();
    if (t == 0) {
        float m = lg[0];
#pragma unroll
        for (int c = 1; c < CC; c++) m = fmaxf(m, lg[c]);
        float se = 0.0f;
#pragma unroll
        for (int c = 0; c < CC; c++) se += expf(lg[c] - m);
        m_s = m;
        lse_s = logf(se);
    }
    __syncthreads();
    if (t < CC) out[b * CC + t] = lg[t] - m_s - lse_s;
}

// ---------------- launch ----------------
extern "C" void kernel_launch(void* const* d_in, const int* in_sizes, int n_in,
                              void* d_out, int out_size) {
    const float* x        = (const float*)d_in[0];
    const void*  ei       = d_in[1];
    const void*  batch    = d_in[2];
    const float* w1  = (const float*)d_in[3];
    const float* as1 = (const float*)d_in[4];
    const float* ad1 = (const float*)d_in[5];
    const float* b1  = (const float*)d_in[6];
    const float* w2  = (const float*)d_in[7];
    const float* as2 = (const float*)d_in[8];
    const float* ad2 = (const float*)d_in[9];
    const float* b2  = (const float*)d_in[10];
    const float* w3  = (const float*)d_in[11];
    const float* as3 = (const float*)d_in[12];
    const float* ad3 = (const float*)d_in[13];
    const float* b3  = (const float*)d_in[14];
    const float* fc1_w = (const float*)d_in[15];
    const float* fc1_b = (const float*)d_in[16];
    const float* fc2_w = (const float*)d_in[17];
    const float* fc2_b = (const float*)d_in[18];
    float* out = (float*)d_out;

    const int EB = 256;
    const int egrid = (ET + EB - 1) / EB;
    const int agrid = (ET + 3) / 4;          // 4 edges per 256-thread block

    // get g_out pointer for layers 2/3 input
    float* g_out_ptr = nullptr;
    cudaGetSymbolAddress((void**)&g_out_ptr, g_out);

    k_detect<<<1, 1>>>(ei);

    // layer 1
    k_gemm_attn<<<NN, DIM>>>(x, w1, as1, ad1);
    k_edge_max<<<egrid, EB>>>(ei);
    k_edge_denom<<<egrid, EB>>>(ei);
    k_edge_aggregate<<<agrid, 256>>>(ei);
    k_norm_relu<<<NN, DIM>>>(b1);

    // layer 2
    k_gemm_attn<<<NN, DIM>>>(g_out_ptr, w2, as2, ad2);
    k_edge_max<<<egrid, EB>>>(ei);
    k_edge_denom<<<egrid, EB>>>(ei);
    k_edge_aggregate<<<agrid, 256>>>(ei);
    k_norm_relu<<<NN, DIM>>>(b2);

    // layer 3
    k_gemm_attn<<<NN, DIM>>>(g_out_ptr, w3, as3, ad3);
    k_edge_max<<<egrid, EB>>>(ei);
    k_edge_denom<<<egrid, EB>>>(ei);
    k_edge_aggregate<<<agrid, 256>>>(ei);
    k_norm_relu<<<NN, DIM>>>(b3);

    // pool + head
    k_zero_pool<<<(GG * DIM + 255) / 256, 256>>>();
    k_pool<<<(NN * DIM + 255) / 256, 256>>>(batch);
    k_head<<<GG, DIM>>>(fc1_w, fc1_b, fc2_w, fc2_b, out);
}

// round 2
// speedup vs baseline: 2.6418x; 2.6418x over previous
#include <cuda_runtime.h>
#include <math.h>

#define NN 50000
#define EE 800000
#define ET (EE + NN)   // edges + self loops
#define DIM 64
#define GG 256
#define CC 10
#define NEG_SLOPE 0.2f
#define NB ((NN + 255) / 256)   // scan blocks = 196

// ---------------- device scratch (static, no allocation) ----------------
__device__ float g_h[NN * DIM];      // h = x @ W  (current layer)
__device__ float g_out[NN * DIM];    // aggregated output / next-layer input
__device__ float g_as[NN];
__device__ float g_ad[NN];
__device__ float g_pool[GG * DIM];
__device__ int   g_is64;

// CSR (built once per launch, reused by all 3 layers)
__device__ int g_deg[NN];
__device__ int g_wcnt[NN];
__device__ int g_row[NN + 1];
__device__ int g_bsum[NB];
__device__ int g_boff[NB];
__device__ int g_esrc[ET];

// ---------------- helpers ----------------
__device__ __forceinline__ float wsum(float v) {
#pragma unroll
    for (int o = 16; o; o >>= 1) v += __shfl_xor_sync(0xffffffffu, v, o);
    return v;
}
__device__ __forceinline__ float wmax(float v) {
#pragma unroll
    for (int o = 16; o; o >>= 1) v = fmaxf(v, __shfl_xor_sync(0xffffffffu, v, o));
    return v;
}

__device__ __forceinline__ void load_edge(const void* ei, int e, int& s, int& d) {
    if (e >= EE) { s = d = e - EE; return; }  // self loop
    if (g_is64) {
        const long long* p = (const long long*)ei;
        s = (int)p[e];
        d = (int)p[EE + e];
    } else {
        const int* p = (const int*)ei;
        s = p[e];
        d = p[EE + e];
    }
}

// ---------------- K0: detect int64 vs int32 indices ----------------
__global__ void k_detect(const void* ei) {
    const int* p = (const int*)ei;
    bool is64 = true;
    for (int k = 0; k < 64; k++) {
        if (p[2 * k + 1] != 0) { is64 = false; break; }
    }
    g_is64 = is64 ? 1 : 0;
}

// ---------------- CSR build ----------------
__global__ void k_zero_deg() {
    int i = blockIdx.x * blockDim.x + threadIdx.x;
    if (i < NN) { g_deg[i] = 0; g_wcnt[i] = 0; }
}

__global__ void k_hist(const void* __restrict__ ei) {
    int e = blockIdx.x * blockDim.x + threadIdx.x;
    if (e >= ET) return;
    int s, d;
    load_edge(ei, e, s, d);
    atomicAdd(&g_deg[d], 1);
}

// per-block exclusive scan of degrees; block total -> g_bsum
__global__ void k_scan_block() {
    __shared__ int sm[256];
    int t = threadIdx.x;
    int i = blockIdx.x * 256 + t;
    int v = (i < NN) ? g_deg[i] : 0;
    sm[t] = v;
    __syncthreads();
#pragma unroll
    for (int off = 1; off < 256; off <<= 1) {
        int tmp = (t >= off) ? sm[t - off] : 0;
        __syncthreads();
        sm[t] += tmp;
        __syncthreads();
    }
    if (i < NN) g_row[i] = sm[t] - v;   // exclusive
    if (t == 255) g_bsum[blockIdx.x] = sm[255];
}

__global__ void k_scan_top() {
    __shared__ int sm[256];
    int t = threadIdx.x;
    int v = (t < NB) ? g_bsum[t] : 0;
    sm[t] = v;
    __syncthreads();
#pragma unroll
    for (int off = 1; off < 256; off <<= 1) {
        int tmp = (t >= off) ? sm[t - off] : 0;
        __syncthreads();
        sm[t] += tmp;
        __syncthreads();
    }
    if (t < NB) g_boff[t] = sm[t] - v;  // exclusive
}

__global__ void k_scan_add() {
    int i = blockIdx.x * blockDim.x + threadIdx.x;
    if (i < NN) g_row[i] += g_boff[i >> 8];
    if (i == 0) g_row[NN] = ET;
}

__global__ void k_scatter(const void* __restrict__ ei) {
    int e = blockIdx.x * blockDim.x + threadIdx.x;
    if (e >= ET) return;
    int s, d;
    load_edge(ei, e, s, d);
    int pos = g_row[d] + atomicAdd(&g_wcnt[d], 1);
    g_esrc[pos] = s;
}

// ---------------- K1: h = xin @ W, attention scalars ----------------
// 256 threads = 4 nodes/block; W staged in smem (16KB)
__global__ void k_gemm_attn(const float* __restrict__ xin,
                            const float* __restrict__ w,
                            const float* __restrict__ a_src,
                            const float* __restrict__ a_dst) {
    __shared__ float ws[DIM * DIM];
    __shared__ float xr[4][DIM];
    __shared__ float smr1[8], smr2[8];
    int tid = threadIdx.x;
    int li = tid >> 6;           // 0..3 local node
    int t = tid & 63;            // 0..63 dim
    int lane = tid & 31;
    int warp = tid >> 5;
    int i = blockIdx.x * 4 + li;

    for (int k = tid; k < DIM * DIM; k += 256) ws[k] = w[k];
    xr[li][t] = (i < NN) ? xin[i * DIM + t] : 0.0f;
    __syncthreads();

    float h = 0.0f;
#pragma unroll
    for (int k = 0; k < DIM; k++) h = fmaf(xr[li][k], ws[k * DIM + t], h);

    float r1 = wsum(h * __ldg(&a_src[t]));
    float r2 = wsum(h * __ldg(&a_dst[t]));
    if (lane == 0) { smr1[warp] = r1; smr2[warp] = r2; }
    __syncthreads();

    if (i < NN) {
        g_h[i * DIM + t] = h;
        if (t == 0) {
            g_as[i] = smr1[li * 2] + smr1[li * 2 + 1];
            g_ad[i] = smr2[li * 2] + smr2[li * 2 + 1];
        }
    }
}

// ---------------- K2: fused softmax + aggregate + bias + l2norm + relu ----------------
// one warp per node; 256 threads = 8 warps/block
__global__ void k_node_agg(const float* __restrict__ bias) {
    int i = blockIdx.x * 8 + (threadIdx.x >> 5);
    int lane = threadIdx.x & 31;
    if (i >= NN) return;
    int beg = g_row[i];
    int end = g_row[i + 1];
    int deg = end - beg;
    float ad_i = g_ad[i];
    float acc0 = 0.0f, acc1 = 0.0f;

    if (deg <= 32) {
        int s_l = 0;
        float e_l = -1e30f;
        if (lane < deg) {
            s_l = g_esrc[beg + lane];
            float v = g_as[s_l] + ad_i;
            e_l = (v > 0.0f) ? v : NEG_SLOPE * v;
        }
        float emax = wmax(e_l);
        float ex = (lane < deg) ? __expf(e_l - emax) : 0.0f;
        float denom = wsum(ex) + 1e-16f;
        float alpha_l = ex / denom;
#pragma unroll 4
        for (int k = 0; k < deg; k++) {
            float a = __shfl_sync(0xffffffffu, alpha_l, k);
            int s = __shfl_sync(0xffffffffu, s_l, k);
            acc0 = fmaf(a, __ldg(&g_h[s * DIM + lane]), acc0);
            acc1 = fmaf(a, __ldg(&g_h[s * DIM + 32 + lane]), acc1);
        }
    } else {
        float emax = -1e30f;
        for (int j = beg + lane; j < end; j += 32) {
            int s = g_esrc[j];
            float v = g_as[s] + ad_i;
            v = (v > 0.0f) ? v : NEG_SLOPE * v;
            emax = fmaxf(emax, v);
        }
        emax = wmax(emax);
        float dsum = 0.0f;
        for (int j = beg + lane; j < end; j += 32) {
            int s = g_esrc[j];
            float v = g_as[s] + ad_i;
            v = (v > 0.0f) ? v : NEG_SLOPE * v;
            dsum += __expf(v - emax);
        }
        float denom = wsum(dsum) + 1e-16f;
        for (int base = beg; base < end; base += 32) {
            int j = base + lane;
            int s_l = 0;
            float ex = 0.0f;
            if (j < end) {
                s_l = g_esrc[j];
                float v = g_as[s_l] + ad_i;
                v = (v > 0.0f) ? v : NEG_SLOPE * v;
                ex = __expf(v - emax) / denom;
            }
            int cnt = min(32, end - base);
            for (int k = 0; k < cnt; k++) {
                float a = __shfl_sync(0xffffffffu, ex, k);
                int s = __shfl_sync(0xffffffffu, s_l, k);
                acc0 = fmaf(a, __ldg(&g_h[s * DIM + lane]), acc0);
                acc1 = fmaf(a, __ldg(&g_h[s * DIM + 32 + lane]), acc1);
            }
        }
    }

    // fused bias + l2 normalize + relu
    float v0 = acc0 + __ldg(&bias[lane]);
    float v1 = acc1 + __ldg(&bias[lane + 32]);
    float ss = wsum(v0 * v0 + v1 * v1);
    float nrm = fmaxf(sqrtf(ss), 1e-12f);
    g_out[i * DIM + lane] = fmaxf(v0 / nrm, 0.0f);
    g_out[i * DIM + 32 + lane] = fmaxf(v1 / nrm, 0.0f);
}

// ---------------- pooling ----------------
__global__ void k_zero_pool() {
    int idx = blockIdx.x * blockDim.x + threadIdx.x;
    if (idx < GG * DIM) g_pool[idx] = 0.0f;
}

#define PCH 16
__global__ void k_pool(const void* __restrict__ batch) {
    int t = threadIdx.x;                 // 0..63 dim
    int n0 = blockIdx.x * PCH;
    int nend = min(n0 + PCH, NN);
    long long cur = -1;
    float acc = 0.0f;
    for (int n = n0; n < nend; n++) {
        long long b = g_is64 ? ((const long long*)batch)[n]
                             : (long long)((const int*)batch)[n];
        if (b != cur) {
            if (cur >= 0) atomicAdd(&g_pool[(int)cur * DIM + t], acc);
            cur = b;
            acc = 0.0f;
        }
        acc += g_out[n * DIM + t];
    }
    if (cur >= 0) atomicAdd(&g_pool[(int)cur * DIM + t], acc);
}

// ---------------- MLP head + log_softmax ----------------
__global__ void k_head(const float* __restrict__ fc1_w, const float* __restrict__ fc1_b,
                       const float* __restrict__ fc2_w, const float* __restrict__ fc2_b,
                       float* __restrict__ out) {
    __shared__ float gv[DIM];
    __shared__ float a1[DIM];
    __shared__ float lg[CC];
    __shared__ float m_s, lse_s;
    int b = blockIdx.x;
    int t = threadIdx.x;
    gv[t] = g_pool[b * DIM + t];
    __syncthreads();

    float a = fc1_b[t];
#pragma unroll
    for (int k = 0; k < DIM; k++) a = fmaf(gv[k], fc1_w[k * DIM + t], a);
    a1[t] = fmaxf(a, 0.0f);
    __syncthreads();

    if (t < CC) {
        float l = fc2_b[t];
#pragma unroll
        for (int k = 0; k < DIM; k++) l = fmaf(a1[k], fc2_w[k * CC + t], l);
        lg[t] = l;
    }
    __syncthreads();
    if (t == 0) {
        float m = lg[0];
#pragma unroll
        for (int c = 1; c < CC; c++) m = fmaxf(m, lg[c]);
        float se = 0.0f;
#pragma unroll
        for (int c = 0; c < CC; c++) se += expf(lg[c] - m);
        m_s = m;
        lse_s = logf(se);
    }
    __syncthreads();
    if (t < CC) out[b * CC + t] = lg[t] - m_s - lse_s;
}

// ---------------- launch ----------------
extern "C" void kernel_launch(void* const* d_in, const int* in_sizes, int n_in,
                              void* d_out, int out_size) {
    const float* x     = (const float*)d_in[0];
    const void*  ei    = d_in[1];
    const void*  batch = d_in[2];
    const float* w1  = (const float*)d_in[3];
    const float* as1 = (const float*)d_in[4];
    const float* ad1 = (const float*)d_in[5];
    const float* b1  = (const float*)d_in[6];
    const float* w2  = (const float*)d_in[7];
    const float* as2 = (const float*)d_in[8];
    const float* ad2 = (const float*)d_in[9];
    const float* b2  = (const float*)d_in[10];
    const float* w3  = (const float*)d_in[11];
    const float* as3 = (const float*)d_in[12];
    const float* ad3 = (const float*)d_in[13];
    const float* b3  = (const float*)d_in[14];
    const float* fc1_w = (const float*)d_in[15];
    const float* fc1_b = (const float*)d_in[16];
    const float* fc2_w = (const float*)d_in[17];
    const float* fc2_b = (const float*)d_in[18];
    float* out = (float*)d_out;

    float* g_out_ptr = nullptr;
    cudaGetSymbolAddress((void**)&g_out_ptr, g_out);

    const int EB = 256;
    const int egrid = (ET + EB - 1) / EB;
    const int ngrid4 = (NN + 3) / 4;     // gemm: 4 nodes/block
    const int ngrid8 = (NN + 7) / 8;     // agg: 8 warps/block

    k_detect<<<1, 1>>>(ei);

    // build CSR once (topology shared by all layers)
    k_zero_deg<<<(NN + 255) / 256, 256>>>();
    k_hist<<<egrid, EB>>>(ei);
    k_scan_block<<<NB, 256>>>();
    k_scan_top<<<1, 256>>>();
    k_scan_add<<<(NN + 255) / 256, 256>>>();
    k_scatter<<<egrid, EB>>>(ei);

    // layer 1
    k_gemm_attn<<<ngrid4, 256>>>(x, w1, as1, ad1);
    k_node_agg<<<ngrid8, 256>>>(b1);
    // layer 2
    k_gemm_attn<<<ngrid4, 256>>>(g_out_ptr, w2, as2, ad2);
    k_node_agg<<<ngrid8, 256>>>(b2);
    // layer 3
    k_gemm_attn<<<ngrid4, 256>>>(g_out_ptr, w3, as3, ad3);
    k_node_agg<<<ngrid8, 256>>>(b3);

    // pool + head
    k_zero_pool<<<(GG * DIM + 255) / 256, 256>>>();
    k_pool<<<(NN + PCH - 1) / PCH, DIM>>>(batch);
    k_head<<<GG, DIM>>>(fc1_w, fc1_b, fc2_w, fc2_b, out);
}

// round 3
// speedup vs baseline: 4.2092x; 1.5933x over previous
#include <cuda_runtime.h>
#include <math.h>

#define NN 50000
#define EE 800000
#define ET (EE + NN)   // edges + self loops
#define DIM 64
#define GG 256
#define CC 10
#define NEG_SLOPE 0.2f
#define NB ((NN + 255) / 256)   // scan blocks = 196

// ---------------- device scratch (static, no allocation) ----------------
__device__ float g_h[NN * DIM];      // h = x @ W  (current layer)
__device__ float g_out[NN * DIM];    // aggregated output / next-layer input
__device__ float g_as[NN];
__device__ float g_ad[NN];
__device__ float g_pool[GG * DIM];
__device__ int   g_is64;

// CSR (built once per launch, reused by all 3 layers)
__device__ int g_deg[NN];
__device__ int g_wcnt[NN];
__device__ int g_row[NN + 1];
__device__ int g_bsum[NB];
__device__ int g_boff[NB];
__device__ int g_esrc[ET];

// ---------------- helpers ----------------
__device__ __forceinline__ float wsum(float v) {
#pragma unroll
    for (int o = 16; o; o >>= 1) v += __shfl_xor_sync(0xffffffffu, v, o);
    return v;
}
__device__ __forceinline__ float wmax(float v) {
#pragma unroll
    for (int o = 16; o; o >>= 1) v = fmaxf(v, __shfl_xor_sync(0xffffffffu, v, o));
    return v;
}

__device__ __forceinline__ void load_edge(const void* ei, int e, int& s, int& d) {
    if (e >= EE) { s = d = e - EE; return; }  // self loop
    if (g_is64) {
        const long long* p = (const long long*)ei;
        s = (int)p[e];
        d = (int)p[EE + e];
    } else {
        const int* p = (const int*)ei;
        s = p[e];
        d = p[EE + e];
    }
}

// ---------------- K0: detect dtype + zero deg/wcnt/pool ----------------
__global__ void k_init(const void* ei) {
    int i = blockIdx.x * blockDim.x + threadIdx.x;
    if (i == 0) {
        const int* p = (const int*)ei;
        bool is64 = true;
        for (int k = 0; k < 64; k++) {
            if (p[2 * k + 1] != 0) { is64 = false; break; }
        }
        g_is64 = is64 ? 1 : 0;
    }
    if (i < NN) { g_deg[i] = 0; g_wcnt[i] = 0; }
    if (i < GG * DIM) g_pool[i] = 0.0f;
}

// ---------------- CSR build ----------------
__global__ void k_hist(const void* __restrict__ ei) {
    int e = blockIdx.x * blockDim.x + threadIdx.x;
    if (e >= ET) return;
    int s, d;
    load_edge(ei, e, s, d);
    atomicAdd(&g_deg[d], 1);
}

__global__ void k_scan_block() {
    __shared__ int sm[256];
    int t = threadIdx.x;
    int i = blockIdx.x * 256 + t;
    int v = (i < NN) ? g_deg[i] : 0;
    sm[t] = v;
    __syncthreads();
#pragma unroll
    for (int off = 1; off < 256; off <<= 1) {
        int tmp = (t >= off) ? sm[t - off] : 0;
        __syncthreads();
        sm[t] += tmp;
        __syncthreads();
    }
    if (i < NN) g_row[i] = sm[t] - v;   // exclusive
    if (t == 255) g_bsum[blockIdx.x] = sm[255];
}

__global__ void k_scan_top() {
    __shared__ int sm[256];
    int t = threadIdx.x;
    int v = (t < NB) ? g_bsum[t] : 0;
    sm[t] = v;
    __syncthreads();
#pragma unroll
    for (int off = 1; off < 256; off <<= 1) {
        int tmp = (t >= off) ? sm[t - off] : 0;
        __syncthreads();
        sm[t] += tmp;
        __syncthreads();
    }
    if (t < NB) g_boff[t] = sm[t] - v;  // exclusive
}

__global__ void k_scan_add() {
    int i = blockIdx.x * blockDim.x + threadIdx.x;
    if (i < NN) g_row[i] += g_boff[i >> 8];
    if (i == 0) g_row[NN] = ET;
}

__global__ void k_scatter(const void* __restrict__ ei) {
    int e = blockIdx.x * blockDim.x + threadIdx.x;
    if (e >= ET) return;
    int s, d;
    load_edge(ei, e, s, d);
    int pos = g_row[d] + atomicAdd(&g_wcnt[d], 1);
    g_esrc[pos] = s;
}

// ---------------- K1: h = xin @ W + attention scalars ----------------
// 256 threads, 32 nodes/block (each 64-lane group computes 8 nodes serially).
// W staged once per block -> 8x less W refetch than 4 nodes/block.
__global__ __launch_bounds__(256) void k_gemm_attn(
        const float* __restrict__ xin, const float* __restrict__ w,
        const float* __restrict__ a_src, const float* __restrict__ a_dst) {
    __shared__ float ws[DIM * DIM];          // 16 KB
    __shared__ float xr[32][DIM];            // 8 KB
    __shared__ float pr1a[32], pr1b[32], pr2a[32], pr2b[32];
    int tid = threadIdx.x;
    int base = blockIdx.x * 32;

    // stage W (float4)
    {
        const float4* w4 = (const float4*)w;
        float4* ws4 = (float4*)ws;
#pragma unroll
        for (int k = tid; k < DIM * DIM / 4; k += 256) ws4[k] = w4[k];
    }
    // stage 32 input rows (float4): 512 float4 total
    {
        const float4* x4 = (const float4*)xin;
        float4* xr4 = (float4*)&xr[0][0];
#pragma unroll
        for (int k = tid; k < 32 * DIM / 4; k += 256) {
            int row = k >> 4;
            float4 v = make_float4(0.f, 0.f, 0.f, 0.f);
            if (base + row < NN) v = x4[(long)(base + row) * 16 + (k & 15)];
            xr4[k] = v;
        }
    }
    __syncthreads();

    int t = tid & 63;                // output dim
    int grp = tid >> 6;              // 0..3
    int wsel = (tid >> 5) & 1;       // warp within group
    float as_t = __ldg(&a_src[t]);
    float ad_t = __ldg(&a_dst[t]);

#pragma unroll
    for (int r = grp; r < 32; r += 4) {
        int i = base + r;
        float h = 0.0f;
#pragma unroll
        for (int k = 0; k < DIM; k++) h = fmaf(xr[r][k], ws[k * DIM + t], h);
        float r1 = wsum(h * as_t);
        float r2 = wsum(h * ad_t);
        if ((tid & 31) == 0) {
            if (wsel == 0) { pr1a[r] = r1; pr2a[r] = r2; }
            else           { pr1b[r] = r1; pr2b[r] = r2; }
        }
        if (i < NN) g_h[i * DIM + t] = h;
    }
    __syncthreads();
    if (tid < 32 && base + tid < NN) {
        g_as[base + tid] = pr1a[tid] + pr1b[tid];
        g_ad[base + tid] = pr2a[tid] + pr2b[tid];
    }
}

// ---------------- K2: fused softmax + aggregate + bias + l2norm + relu ----------------
// one warp per node; float4 gathers, 2 edges per iteration
__global__ __launch_bounds__(256) void k_node_agg(const float* __restrict__ bias) {
    int i = blockIdx.x * 8 + (threadIdx.x >> 5);
    int lane = threadIdx.x & 31;
    if (i >= NN) return;
    int sub = lane >> 4;     // which edge of the pair
    int q = lane & 15;       // float4 chunk (dims 4q..4q+3)
    int beg = g_row[i];
    int end = g_row[i + 1];
    int deg = end - beg;
    float ad_i = g_ad[i];
    const float4* h4 = (const float4*)g_h;
    float4 acc = make_float4(0.f, 0.f, 0.f, 0.f);

    if (deg <= 32) {
        int s_l = 0;
        float e_l = -1e30f;
        if (lane < deg) {
            s_l = g_esrc[beg + lane];
            float v = g_as[s_l] + ad_i;
            e_l = (v > 0.0f) ? v : NEG_SLOPE * v;
        }
        float emax = wmax(e_l);
        float ex = (lane < deg) ? __expf(e_l - emax) : 0.0f;
        float denom = wsum(ex) + 1e-16f;
        float alpha_l = ex / denom;   // 0 for lanes >= deg
#pragma unroll 4
        for (int k = 0; k < deg; k += 2) {
            int kk = k + sub;         // <= 31 always
            float a = __shfl_sync(0xffffffffu, alpha_l, kk);
            int s = __shfl_sync(0xffffffffu, s_l, kk);
            float4 hv = __ldg(&h4[(long)s * 16 + q]);
            acc.x = fmaf(a, hv.x, acc.x);
            acc.y = fmaf(a, hv.y, acc.y);
            acc.z = fmaf(a, hv.z, acc.z);
            acc.w = fmaf(a, hv.w, acc.w);
        }
    } else {
        float emax = -1e30f;
        for (int j = beg + lane; j < end; j += 32) {
            int s = g_esrc[j];
            float v = g_as[s] + ad_i;
            v = (v > 0.0f) ? v : NEG_SLOPE * v;
            emax = fmaxf(emax, v);
        }
        emax = wmax(emax);
        float dsum = 0.0f;
        for (int j = beg + lane; j < end; j += 32) {
            int s = g_esrc[j];
            float v = g_as[s] + ad_i;
            v = (v > 0.0f) ? v : NEG_SLOPE * v;
            dsum += __expf(v - emax);
        }
        float denom = wsum(dsum) + 1e-16f;
        for (int cbase = beg; cbase < end; cbase += 32) {
            int j = cbase + lane;
            int s_l = 0;
            float alpha_l = 0.0f;
            if (j < end) {
                s_l = g_esrc[j];
                float v = g_as[s_l] + ad_i;
                v = (v > 0.0f) ? v : NEG_SLOPE * v;
                alpha_l = __expf(v - emax) / denom;
            }
            int cnt = min(32, end - cbase);
#pragma unroll 4
            for (int k = 0; k < cnt; k += 2) {
                int kk = k + sub;
                float a = __shfl_sync(0xffffffffu, alpha_l, kk);
                int s = __shfl_sync(0xffffffffu, s_l, kk);
                float4 hv = __ldg(&h4[(long)s * 16 + q]);
                acc.x = fmaf(a, hv.x, acc.x);
                acc.y = fmaf(a, hv.y, acc.y);
                acc.z = fmaf(a, hv.z, acc.z);
                acc.w = fmaf(a, hv.w, acc.w);
            }
        }
    }

    // combine the two edge-parity halves (lane xor 16 has same q, other sub)
    acc.x += __shfl_xor_sync(0xffffffffu, acc.x, 16);
    acc.y += __shfl_xor_sync(0xffffffffu, acc.y, 16);
    acc.z += __shfl_xor_sync(0xffffffffu, acc.z, 16);
    acc.w += __shfl_xor_sync(0xffffffffu, acc.w, 16);

    // bias + l2 normalize + relu (values duplicated across halves)
    float4 b4 = __ldg(&((const float4*)bias)[q]);
    float4 v;
    v.x = acc.x + b4.x; v.y = acc.y + b4.y;
    v.z = acc.z + b4.z; v.w = acc.w + b4.w;
    float dot = v.x * v.x + v.y * v.y + v.z * v.z + v.w * v.w;
    float ss = wsum(dot) * 0.5f;      // halves are duplicates
    float inv = 1.0f / fmaxf(sqrtf(ss), 1e-12f);
    if (sub == 0) {
        float4 o;
        o.x = fmaxf(v.x * inv, 0.0f);
        o.y = fmaxf(v.y * inv, 0.0f);
        o.z = fmaxf(v.z * inv, 0.0f);
        o.w = fmaxf(v.w * inv, 0.0f);
        ((float4*)g_out)[(long)i * 16 + q] = o;
    }
}

// ---------------- pooling (batch is sorted; run-length accumulate) ----------------
#define PCH 16
__global__ void k_pool(const void* __restrict__ batch) {
    int t = threadIdx.x;                 // 0..63 dim
    int n0 = blockIdx.x * PCH;
    int nend = min(n0 + PCH, NN);
    long long cur = -1;
    float acc = 0.0f;
    for (int n = n0; n < nend; n++) {
        long long b = g_is64 ? ((const long long*)batch)[n]
                             : (long long)((const int*)batch)[n];
        if (b != cur) {
            if (cur >= 0) atomicAdd(&g_pool[(int)cur * DIM + t], acc);
            cur = b;
            acc = 0.0f;
        }
        acc += g_out[n * DIM + t];
    }
    if (cur >= 0) atomicAdd(&g_pool[(int)cur * DIM + t], acc);
}

// ---------------- MLP head + log_softmax ----------------
__global__ void k_head(const float* __restrict__ fc1_w, const float* __restrict__ fc1_b,
                       const float* __restrict__ fc2_w, const float* __restrict__ fc2_b,
                       float* __restrict__ out) {
    __shared__ float gv[DIM];
    __shared__ float a1[DIM];
    __shared__ float lg[CC];
    __shared__ float m_s, lse_s;
    int b = blockIdx.x;
    int t = threadIdx.x;
    gv[t] = g_pool[b * DIM + t];
    __syncthreads();

    float a = fc1_b[t];
#pragma unroll
    for (int k = 0; k < DIM; k++) a = fmaf(gv[k], fc1_w[k * DIM + t], a);
    a1[t] = fmaxf(a, 0.0f);
    __syncthreads();

    if (t < CC) {
        float l = fc2_b[t];
#pragma unroll
        for (int k = 0; k < DIM; k++) l = fmaf(a1[k], fc2_w[k * CC + t], l);
        lg[t] = l;
    }
    __syncthreads();
    if (t == 0) {
        float m = lg[0];
#pragma unroll
        for (int c = 1; c < CC; c++) m = fmaxf(m, lg[c]);
        float se = 0.0f;
#pragma unroll
        for (int c = 0; c < CC; c++) se += expf(lg[c] - m);
        m_s = m;
        lse_s = logf(se);
    }
    __syncthreads();
    if (t < CC) out[b * CC + t] = lg[t] - m_s - lse_s;
}

// ---------------- launch ----------------
extern "C" void kernel_launch(void* const* d_in, const int* in_sizes, int n_in,
                              void* d_out, int out_size) {
    const float* x     = (const float*)d_in[0];
    const void*  ei    = d_in[1];
    const void*  batch = d_in[2];
    const float* w1  = (const float*)d_in[3];
    const float* as1 = (const float*)d_in[4];
    const float* ad1 = (const float*)d_in[5];
    const float* b1  = (const float*)d_in[6];
    const float* w2  = (const float*)d_in[7];
    const float* as2 = (const float*)d_in[8];
    const float* ad2 = (const float*)d_in[9];
    const float* b2  = (const float*)d_in[10];
    const float* w3  = (const float*)d_in[11];
    const float* as3 = (const float*)d_in[12];
    const float* ad3 = (const float*)d_in[13];
    const float* b3  = (const float*)d_in[14];
    const float* fc1_w = (const float*)d_in[15];
    const float* fc1_b = (const float*)d_in[16];
    const float* fc2_w = (const float*)d_in[17];
    const float* fc2_b = (const float*)d_in[18];
    float* out = (float*)d_out;

    float* g_out_ptr = nullptr;
    cudaGetSymbolAddress((void**)&g_out_ptr, g_out);

    const int EB = 256;
    const int egrid = (ET + EB - 1) / EB;
    const int ggrid = (NN + 31) / 32;    // gemm: 32 nodes/block
    const int agrid = (NN + 7) / 8;      // agg: 8 warps/block

    k_init<<<(NN + 255) / 256, 256>>>(ei);

    // build CSR once (topology shared by all layers)
    k_hist<<<egrid, EB>>>(ei);
    k_scan_block<<<NB, 256>>>();
    k_scan_top<<<1, 256>>>();
    k_scan_add<<<(NN + 255) / 256, 256>>>();
    k_scatter<<<egrid, EB>>>(ei);

    // layer 1
    k_gemm_attn<<<ggrid, 256>>>(x, w1, as1, ad1);
    k_node_agg<<<agrid, 256>>>(b1);
    // layer 2
    k_gemm_attn<<<ggrid, 256>>>(g_out_ptr, w2, as2, ad2);
    k_node_agg<<<agrid, 256>>>(b2);
    // layer 3
    k_gemm_attn<<<ggrid, 256>>>(g_out_ptr, w3, as3, ad3);
    k_node_agg<<<agrid, 256>>>(b3);

    // pool + head
    k_pool<<<(NN + PCH - 1) / PCH, DIM>>>(batch);
    k_head<<<GG, DIM>>>(fc1_w, fc1_b, fc2_w, fc2_b, out);
}